// round 4
// baseline (speedup 1.0000x reference)
#include <cuda_runtime.h>

// 3-layer LSTM (IN=5, H=50) + FC(50->1), B=1024, T=512.
// Fused persistent kernel v3: j-ownership + 2-way K-split + 2 batch slots
// per thread. Thread (j, ks, bg) accumulates gate rows {j, j+50, j+100,
// j+150} over K-half ks for batches {2bg, 2bg+1}; one shfl.bfly(4) combines
// the K halves; thread (j, ks, bg) then owns the full c/h update for
// batch 2bg+ks (cell state lives in 3 registers for the whole run).
// 400 gate threads = 12.5 warps; spare threads prefetch x(t+1).
// v vectors double-buffered on t parity; 3 barriers/step.

#define T_STEPS   512
#define IN_DIM    5
#define HID       50
#define NB        7
#define NTHREADS  448
#define GRID      148
#define WSTR      816          // floats per kq block: 200 rows * 4 + 16 pad
                               // (816 mod 32 = 16 -> ks0/ks1 kq blocks land on
                               //  disjoint bank halves)

// smem offsets (floats)
enum {
    W1_OFF = 0,                // 14 * 816
    W2_OFF = 11424,            // 25 * 816
    W3_OFF = 31824,            // 25 * 816
    BS_OFF = 52224,            // 3 * 200 combined biases
    V1_OFF = 52824,            // 2 bufs * 7 * 56   [x(5),pad,h1(50)]
    V2_OFF = 53608,            // 2 bufs * 7 * 100  [h1,h2]
    V3_OFF = 55008,            // 2 bufs * 7 * 100  [h2,h3]
    SH_FLOATS = 56408          // 225632 bytes
};
#define V1B 392
#define V2B 700
#define V3B 700

typedef unsigned long long ull;

__device__ __forceinline__ ull ffma2(ull a, ull b, ull c) {
    ull d;
    asm("fma.rn.f32x2 %0, %1, %2, %3;" : "=l"(d) : "l"(a), "l"(b), "l"(c));
    return d;
}
__device__ __forceinline__ float fast_ex2(float x) {
    float y; asm("ex2.approx.ftz.f32 %0, %1;" : "=f"(y) : "f"(x)); return y;
}
__device__ __forceinline__ float fast_rcp(float x) {
    float y; asm("rcp.approx.ftz.f32 %0, %1;" : "=f"(y) : "f"(x)); return y;
}
__device__ __forceinline__ float sigm(float x) {
    return fast_rcp(1.0f + fast_ex2(-1.4426950408889634f * x));
}
__device__ __forceinline__ float tanh_acc(float x) {
    float r = fast_rcp(1.0f + fast_ex2(-2.8853900817779268f * x));
    return r + r - 1.0f;
}
__device__ __forceinline__ float lohi(ull a) {
    float lo, hi;
    asm("mov.b64 {%0, %1}, %2;" : "=f"(lo), "=f"(hi) : "l"(a));
    return lo + hi;
}

// Accumulate 4 gate rows over kq = ks, ks+2, ... < KQ for the thread's two
// batch slots. acc[g][slot] are packed f32x2 partial sums.
template<int KQ>
__device__ __forceinline__ void gate_accum(const float* __restrict__ shw,
                                           const float* __restrict__ v0,
                                           const float* __restrict__ v1,
                                           int j, int ks, ull acc[4][2]) {
#pragma unroll
    for (int g = 0; g < 4; g++) { acc[g][0] = 0ull; acc[g][1] = 0ull; }
#pragma unroll 2
    for (int kq = ks; kq < KQ; kq += 2) {
        const ulonglong2* wq =
            reinterpret_cast<const ulonglong2*>(shw + kq * WSTR);
        ulonglong2 w0 = wq[j];
        ulonglong2 w1 = wq[j + HID];
        ulonglong2 w2 = wq[j + 2 * HID];
        ulonglong2 w3 = wq[j + 3 * HID];
        ulonglong2 va = *reinterpret_cast<const ulonglong2*>(v0 + kq * 4);
        ulonglong2 vb = *reinterpret_cast<const ulonglong2*>(v1 + kq * 4);
        acc[0][0] = ffma2(w0.x, va.x, acc[0][0]);
        acc[0][0] = ffma2(w0.y, va.y, acc[0][0]);
        acc[1][0] = ffma2(w1.x, va.x, acc[1][0]);
        acc[1][0] = ffma2(w1.y, va.y, acc[1][0]);
        acc[2][0] = ffma2(w2.x, va.x, acc[2][0]);
        acc[2][0] = ffma2(w2.y, va.y, acc[2][0]);
        acc[3][0] = ffma2(w3.x, va.x, acc[3][0]);
        acc[3][0] = ffma2(w3.y, va.y, acc[3][0]);
        acc[0][1] = ffma2(w0.x, vb.x, acc[0][1]);
        acc[0][1] = ffma2(w0.y, vb.y, acc[0][1]);
        acc[1][1] = ffma2(w1.x, vb.x, acc[1][1]);
        acc[1][1] = ffma2(w1.y, vb.y, acc[1][1]);
        acc[2][1] = ffma2(w2.x, vb.x, acc[2][1]);
        acc[2][1] = ffma2(w2.y, vb.y, acc[2][1]);
        acc[3][1] = ffma2(w3.x, vb.x, acc[3][1]);
        acc[3][1] = ffma2(w3.y, vb.y, acc[3][1]);
    }
}

// Combine K halves across the ks partner (lane xor 4); add bias; update c;
// write h to one or two smem destinations.
__device__ __forceinline__ void reduce_update(ull acc[4][2], int ks,
                                              unsigned mask, const float* bz,
                                              bool dovalid, float& c,
                                              float* sh, int d1, int d2,
                                              bool has2) {
    float tot[4];
#pragma unroll
    for (int g = 0; g < 4; g++) {
        float own   = lohi(acc[g][ks]);
        float other = lohi(acc[g][ks ^ 1]);
        float got = __shfl_xor_sync(mask, other, 4);
        tot[g] = own + got + bz[g];
    }
    if (dovalid) {
        float iv = sigm(tot[0]);
        float fv = sigm(tot[1]);
        float gv = tanh_acc(tot[2]);
        float ov = sigm(tot[3]);
        c = fv * c + iv * gv;
        float h = ov * tanh_acc(c);
        sh[d1] = h;
        if (has2) sh[d2] = h;
    }
}

__global__ void __launch_bounds__(NTHREADS, 1)
lstm3_fused_kernel(const float* __restrict__ x,
                   const float* __restrict__ Wih1, const float* __restrict__ Whh1,
                   const float* __restrict__ bih1, const float* __restrict__ bhh1,
                   const float* __restrict__ Wih2, const float* __restrict__ Whh2,
                   const float* __restrict__ bih2, const float* __restrict__ bhh2,
                   const float* __restrict__ Wih3, const float* __restrict__ Whh3,
                   const float* __restrict__ bih3, const float* __restrict__ bhh3,
                   const float* __restrict__ fcW, const float* __restrict__ fcb,
                   float* __restrict__ out) {
    extern __shared__ float sh[];
    const int tid = threadIdx.x;
    const int bid = blockIdx.x;

    int b0, cnt;
    if (bid < 136) { b0 = bid * 7;               cnt = 7; }
    else           { b0 = 952 + (bid - 136) * 6; cnt = 6; }

    // zero v buffers
    for (int i = V1_OFF + tid; i < SH_FLOATS; i += NTHREADS) sh[i] = 0.0f;

    // stage weights: [kq][row][k&3], kq-stride WSTR
    for (int idx = tid; idx < 200 * 56; idx += NTHREADS) {
        int g = idx / 56, k = idx - g * 56;
        float v;
        if (k < IN_DIM)       v = Wih1[g * IN_DIM + k];
        else if (k == IN_DIM) v = 0.0f;
        else                  v = Whh1[g * HID + (k - 6)];
        sh[W1_OFF + (k >> 2) * WSTR + g * 4 + (k & 3)] = v;
    }
    for (int idx = tid; idx < 200 * 100; idx += NTHREADS) {
        int g = idx / 100, k = idx - g * 100;
        float v = (k < HID) ? Wih2[g * HID + k] : Whh2[g * HID + (k - HID)];
        sh[W2_OFF + (k >> 2) * WSTR + g * 4 + (k & 3)] = v;
    }
    for (int idx = tid; idx < 200 * 100; idx += NTHREADS) {
        int g = idx / 100, k = idx - g * 100;
        float v = (k < HID) ? Wih3[g * HID + k] : Whh3[g * HID + (k - HID)];
        sh[W3_OFF + (k >> 2) * WSTR + g * 4 + (k & 3)] = v;
    }
    for (int idx = tid; idx < 600; idx += NTHREADS) {
        int l = idx / 200, g = idx - l * 200;
        const float* bi = (l == 0) ? bih1 : (l == 1) ? bih2 : bih3;
        const float* bh = (l == 0) ? bhh1 : (l == 1) ? bhh2 : bhh3;
        sh[BS_OFF + idx] = bi[g] + bh[g];
    }
    // x(t=0) into v1 buf0
    if (tid < NB * IN_DIM) {
        int b = tid / IN_DIM, d = tid - b * IN_DIM;
        if (b < cnt)
            sh[V1_OFF + b * 56 + d] = x[(size_t)(b0 + b) * T_STEPS * IN_DIM + d];
    }
    __syncthreads();

    const bool gate = (tid < 400);
    const int j  = tid >> 3;          // 0..49
    const int ks = (tid >> 2) & 1;    // 0..1 (lane bit 2 -> shfl.bfly 4)
    const int bg = tid & 3;           // 0..3
    const int bs0 = 2 * bg;                       // slot-0 batch
    const int bs1 = (2 * bg + 1 < NB) ? 2 * bg + 1 : NB - 1;  // clamped
    const int myb = 2 * bg + ks;                  // batch this thread updates
    const bool dov = gate && (myb < cnt) && (2 * bg + ks < NB);
    const unsigned mask = (tid < 384) ? 0xFFFFFFFFu : 0x0000FFFFu;

    float bz1[4], bz2[4], bz3[4];
    if (gate) {
#pragma unroll
        for (int g = 0; g < 4; g++) {
            bz1[g] = sh[BS_OFF +       g * HID + j];
            bz2[g] = sh[BS_OFF + 200 + g * HID + j];
            bz3[g] = sh[BS_OFF + 400 + g * HID + j];
        }
    }
    float c1 = 0.f, c2 = 0.f, c3 = 0.f;

    // spare threads (400..447): x prefetch slots
    int pb = 0, pd = 0; bool pth = false;
    if (tid >= 400 && tid < 400 + NB * IN_DIM) {
        int i = tid - 400;
        pb = i / IN_DIM; pd = i - pb * IN_DIM;
        pth = (pb < cnt);
    }

    for (int t = 0; t < T_STEPS; t++) {
        const int p = t & 1, q = p ^ 1;
        float xv = 0.0f;
        const bool pv = pth && (t + 1 < T_STEPS);

        // ---- layer 1: read v1[p] = [x(t), h1(t-1)] ----
        if (gate) {
            ull acc[4][2];
            const float* vb = sh + V1_OFF + p * V1B;
            gate_accum<14>(sh + W1_OFF, vb + bs0 * 56, vb + bs1 * 56, j, ks, acc);
            reduce_update(acc, ks, mask, bz1, dov, c1, sh,
                          V1_OFF + q * V1B + myb * 56 + 6 + j,
                          V2_OFF + p * V2B + myb * 100 + j, true);
        } else if (pv) {
            xv = x[(size_t)(b0 + pb) * T_STEPS * IN_DIM + (t + 1) * IN_DIM + pd];
        }
        __syncthreads();

        // ---- layer 2: read v2[p] = [h1(t), h2(t-1)] ----
        if (gate) {
            ull acc[4][2];
            const float* vb = sh + V2_OFF + p * V2B;
            gate_accum<25>(sh + W2_OFF, vb + bs0 * 100, vb + bs1 * 100, j, ks, acc);
            reduce_update(acc, ks, mask, bz2, dov, c2, sh,
                          V2_OFF + q * V2B + myb * 100 + HID + j,
                          V3_OFF + p * V3B + myb * 100 + j, true);
        } else if (pv) {
            sh[V1_OFF + q * V1B + pb * 56 + pd] = xv;   // commit x(t+1)
        }
        __syncthreads();

        // ---- layer 3: read v3[p] = [h2(t), h3(t-1)] ----
        if (gate) {
            ull acc[4][2];
            const float* vb = sh + V3_OFF + p * V3B;
            gate_accum<25>(sh + W3_OFF, vb + bs0 * 100, vb + bs1 * 100, j, ks, acc);
            reduce_update(acc, ks, mask, bz3, dov, c3, sh,
                          V3_OFF + q * V3B + myb * 100 + HID + j, 0, false);
        }
        __syncthreads();
    }

    // FC: final h3 in v3 buf0 (t=511 wrote parity q=0)
    if (tid < cnt) {
        float a = fcb[0];
#pragma unroll
        for (int jj = 0; jj < HID; jj++)
            a += fcW[jj] * sh[V3_OFF + tid * 100 + HID + jj];
        out[b0 + tid] = a;
    }
}

extern "C" void kernel_launch(void* const* d_in, const int* in_sizes, int n_in,
                              void* d_out, int out_size) {
    const float* x    = (const float*)d_in[0];
    const float* Wih1 = (const float*)d_in[1];
    const float* Whh1 = (const float*)d_in[2];
    const float* bih1 = (const float*)d_in[3];
    const float* bhh1 = (const float*)d_in[4];
    const float* Wih2 = (const float*)d_in[5];
    const float* Whh2 = (const float*)d_in[6];
    const float* bih2 = (const float*)d_in[7];
    const float* bhh2 = (const float*)d_in[8];
    const float* Wih3 = (const float*)d_in[9];
    const float* Whh3 = (const float*)d_in[10];
    const float* bih3 = (const float*)d_in[11];
    const float* bhh3 = (const float*)d_in[12];
    const float* fcW  = (const float*)d_in[13];
    const float* fcb  = (const float*)d_in[14];

    size_t shbytes = (size_t)SH_FLOATS * sizeof(float);
    cudaFuncSetAttribute(lstm3_fused_kernel,
                         cudaFuncAttributeMaxDynamicSharedMemorySize,
                         (int)shbytes);
    lstm3_fused_kernel<<<GRID, NTHREADS, shbytes>>>(
        x, Wih1, Whh1, bih1, bhh1, Wih2, Whh2, bih2, bhh2,
        Wih3, Whh3, bih3, bhh3, fcW, fcb, (float*)d_out);
}

// round 5
// speedup vs baseline: 1.2653x; 1.2653x over previous
#include <cuda_runtime.h>

// 3-layer LSTM (IN=5, H=50) + FC(50->1), B=1024, T=512.
// Fused persistent kernel v4 = R2 architecture with the local-memory bug fixed.
// Thread (j, ks): accumulates gate rows {j, j+50, j+100, j+150} over K-slice
// kq = ks, ks+4, ... for ALL 7 batch elems (28 packed f32x2 accumulators);
// 2-round shfl.bfly combines the 4 K-partials; the thread then updates
// batches {ks, ks+4} fully in registers (cell state never touches smem).
// CRITICAL: no register array is ever indexed by a runtime value — batch
// extraction goes through a 3-SEL pick4(ks) chain, keeping everything in
// registers (R2/R3 regressions were local-memory spills from dynamic
// indexing, visible as L2=13-15% in ncu).

#define T_STEPS   512
#define IN_DIM    5
#define HID       50
#define NB        7
#define NTHREADS  256
#define GRID      148
#define WSTR      808          // floats per kq block (200 rows * 4 + 8 pad)
                               // ks-stride = 808*4B == 32B mod 128B -> each
                               // 8-lane phase (2 j x 4 ks) hits 32 distinct banks

// smem offsets (floats)
enum {
    W1_OFF = 0,                // 14 kq * 808
    W2_OFF = 11312,            // 25 kq * 808
    W3_OFF = 31512,
    BS_OFF = 51712,            // 3 * 200 combined biases
    V1_OFF = 52312,            // 2 bufs * 7 * 56   [x(5),pad,h1(50)]
    V2_OFF = 53096,            // 2 bufs * 7 * 100  [h1,h2]
    V3_OFF = 54496,            // 2 bufs * 7 * 100  [h2,h3]
    SH_FLOATS = 55896          // 223584 bytes
};
#define V1B 392
#define V2B 700
#define V3B 700

typedef unsigned long long ull;

__device__ __forceinline__ ull ffma2(ull a, ull b, ull c) {
    ull d;
    asm("fma.rn.f32x2 %0, %1, %2, %3;" : "=l"(d) : "l"(a), "l"(b), "l"(c));
    return d;
}
__device__ __forceinline__ float fast_ex2(float x) {
    float y; asm("ex2.approx.ftz.f32 %0, %1;" : "=f"(y) : "f"(x)); return y;
}
__device__ __forceinline__ float fast_rcp(float x) {
    float y; asm("rcp.approx.ftz.f32 %0, %1;" : "=f"(y) : "f"(x)); return y;
}
__device__ __forceinline__ float sigm(float x) {
    return fast_rcp(1.0f + fast_ex2(-1.4426950408889634f * x));
}
__device__ __forceinline__ float tanh_acc(float x) {
    float r = fast_rcp(1.0f + fast_ex2(-2.8853900817779268f * x));
    return r + r - 1.0f;
}
__device__ __forceinline__ float lohi(ull a) {
    float lo, hi;
    asm("mov.b64 {%0, %1}, %2;" : "=f"(lo), "=f"(hi) : "l"(a));
    return lo + hi;
}
// 4-way select without memory: 3 SEL instructions.
__device__ __forceinline__ float pick4(float a0, float a1, float a2, float a3,
                                       int k) {
    float x = (k & 1) ? a1 : a0;
    float y = (k & 1) ? a3 : a2;
    return (k & 2) ? y : x;
}

// Accumulate 4 gate rows (j, j+50, j+100, j+150) over kq = ks, ks+4, ... < KQ
// for all NB batches. s[g][b] = this thread's K-slice partial (all indices
// compile-time constant after unrolling).
template<int KQ, int VS>
__device__ __forceinline__ void gate_accum(const float* __restrict__ shw,
                                           const float* __restrict__ shv,
                                           int j, int ks, float s[4][NB]) {
    ull acc[4][NB];
#pragma unroll
    for (int g = 0; g < 4; g++)
#pragma unroll
        for (int b = 0; b < NB; b++) acc[g][b] = 0ull;

#pragma unroll 2
    for (int kq = ks; kq < KQ; kq += 4) {
        const ulonglong2* wq =
            reinterpret_cast<const ulonglong2*>(shw + kq * WSTR);
        ulonglong2 w0 = wq[j];
        ulonglong2 w1 = wq[j + HID];
        ulonglong2 w2 = wq[j + 2 * HID];
        ulonglong2 w3 = wq[j + 3 * HID];
#pragma unroll
        for (int b = 0; b < NB; b++) {
            ulonglong2 v = *reinterpret_cast<const ulonglong2*>(
                shv + b * VS + kq * 4);
            acc[0][b] = ffma2(w0.x, v.x, acc[0][b]);
            acc[0][b] = ffma2(w0.y, v.y, acc[0][b]);
            acc[1][b] = ffma2(w1.x, v.x, acc[1][b]);
            acc[1][b] = ffma2(w1.y, v.y, acc[1][b]);
            acc[2][b] = ffma2(w2.x, v.x, acc[2][b]);
            acc[2][b] = ffma2(w2.y, v.y, acc[2][b]);
            acc[3][b] = ffma2(w3.x, v.x, acc[3][b]);
            acc[3][b] = ffma2(w3.y, v.y, acc[3][b]);
        }
    }
#pragma unroll
    for (int g = 0; g < 4; g++)
#pragma unroll
        for (int b = 0; b < NB; b++) s[g][b] = lohi(acc[g][b]);
}

// Butterfly-combine the 4 K-partials (constant indices only).
__device__ __forceinline__ void reduce4(float s[4][NB], unsigned mask) {
#pragma unroll
    for (int g = 0; g < 4; g++)
#pragma unroll
        for (int b = 0; b < NB; b++) {
            s[g][b] += __shfl_xor_sync(mask, s[g][b], 1);
            s[g][b] += __shfl_xor_sync(mask, s[g][b], 2);
        }
}

// Extract batch ks (slot 0) and ks+4 (slot 1) gate sums via SEL chains,
// apply activations + c/h update.
__device__ __forceinline__ void update_pair(const float s[4][NB], int ks,
                                            const float* bz,
                                            float& c0, float& c1, bool two,
                                            float* sh,
                                            int d1a, int d2a, bool has2,
                                            int d1b, int d2b) {
    float t0[4], t1[4];
#pragma unroll
    for (int g = 0; g < 4; g++) {
        t0[g] = pick4(s[g][0], s[g][1], s[g][2], s[g][3], ks) + bz[g];
        t1[g] = pick4(s[g][4], s[g][5], s[g][6], s[g][6], ks) + bz[g];
    }
    {
        float iv = sigm(t0[0]);
        float fv = sigm(t0[1]);
        float gv = tanh_acc(t0[2]);
        float ov = sigm(t0[3]);
        c0 = fv * c0 + iv * gv;
        float h = ov * tanh_acc(c0);
        sh[d1a] = h;
        if (has2) sh[d2a] = h;
    }
    if (two) {
        float iv = sigm(t1[0]);
        float fv = sigm(t1[1]);
        float gv = tanh_acc(t1[2]);
        float ov = sigm(t1[3]);
        c1 = fv * c1 + iv * gv;
        float h = ov * tanh_acc(c1);
        sh[d1b] = h;
        if (has2) sh[d2b] = h;
    }
}

__global__ void __launch_bounds__(NTHREADS, 1)
lstm3_fused_kernel(const float* __restrict__ x,
                   const float* __restrict__ Wih1, const float* __restrict__ Whh1,
                   const float* __restrict__ bih1, const float* __restrict__ bhh1,
                   const float* __restrict__ Wih2, const float* __restrict__ Whh2,
                   const float* __restrict__ bih2, const float* __restrict__ bhh2,
                   const float* __restrict__ Wih3, const float* __restrict__ Whh3,
                   const float* __restrict__ bih3, const float* __restrict__ bhh3,
                   const float* __restrict__ fcW, const float* __restrict__ fcb,
                   float* __restrict__ out) {
    extern __shared__ float sh[];
    const int tid = threadIdx.x;
    const int bid = blockIdx.x;

    int b0, cnt;
    if (bid < 136) { b0 = bid * 7;               cnt = 7; }
    else           { b0 = 952 + (bid - 136) * 6; cnt = 6; }

    // zero v buffers (both parities)
    for (int i = V1_OFF + tid; i < SH_FLOATS; i += NTHREADS) sh[i] = 0.0f;

    // stage weights: [kq][row][k&3], kq-stride WSTR
    for (int idx = tid; idx < 200 * 56; idx += NTHREADS) {
        int g = idx / 56, k = idx - g * 56;
        float v;
        if (k < IN_DIM)       v = Wih1[g * IN_DIM + k];
        else if (k == IN_DIM) v = 0.0f;
        else                  v = Whh1[g * HID + (k - 6)];
        sh[W1_OFF + (k >> 2) * WSTR + g * 4 + (k & 3)] = v;
    }
    for (int idx = tid; idx < 200 * 100; idx += NTHREADS) {
        int g = idx / 100, k = idx - g * 100;
        float v = (k < HID) ? Wih2[g * HID + k] : Whh2[g * HID + (k - HID)];
        sh[W2_OFF + (k >> 2) * WSTR + g * 4 + (k & 3)] = v;
    }
    for (int idx = tid; idx < 200 * 100; idx += NTHREADS) {
        int g = idx / 100, k = idx - g * 100;
        float v = (k < HID) ? Wih3[g * HID + k] : Whh3[g * HID + (k - HID)];
        sh[W3_OFF + (k >> 2) * WSTR + g * 4 + (k & 3)] = v;
    }
    for (int idx = tid; idx < 600; idx += NTHREADS) {
        int l = idx / 200, g = idx - l * 200;
        const float* bi = (l == 0) ? bih1 : (l == 1) ? bih2 : bih3;
        const float* bh = (l == 0) ? bhh1 : (l == 1) ? bhh2 : bhh3;
        sh[BS_OFF + idx] = bi[g] + bh[g];
    }
    // x(t=0) into v1 buf0
    if (tid < NB * IN_DIM) {
        int b = tid / IN_DIM, d = tid - b * IN_DIM;
        if (b < cnt)
            sh[V1_OFF + b * 56 + d] = x[(size_t)(b0 + b) * T_STEPS * IN_DIM + d];
    }
    __syncthreads();

    const bool gate = (tid < 200);
    const int j  = tid >> 2;        // 0..49
    const int ks = tid & 3;         // 0..3
    const unsigned mask = (tid < 192) ? 0xFFFFFFFFu : 0x000000FFu;
    const bool two = (ks < 3);      // batch ks+4 exists (slot < 7)
    const int ob0 = ks, ob1 = ks + 4;

    float bz1[4], bz2[4], bz3[4];
    if (gate) {
#pragma unroll
        for (int g = 0; g < 4; g++) {
            bz1[g] = sh[BS_OFF +       g * HID + j];
            bz2[g] = sh[BS_OFF + 200 + g * HID + j];
            bz3[g] = sh[BS_OFF + 400 + g * HID + j];
        }
    }
    // cell states in registers: batches {ks, ks+4} x 3 layers
    float c1a = 0.f, c1b = 0.f, c2a = 0.f, c2b = 0.f, c3a = 0.f, c3b = 0.f;

    // spare threads (200..255): x prefetch slots
    int pb = 0, pd = 0; bool pth = false;
    if (tid >= 200 && tid < 200 + NB * IN_DIM) {
        int i = tid - 200;
        pb = i / IN_DIM; pd = i - pb * IN_DIM;
        pth = (pb < cnt);
    }

    for (int t = 0; t < T_STEPS; t++) {
        const int p = t & 1, q = p ^ 1;
        float xv = 0.0f;
        const bool pv = pth && (t + 1 < T_STEPS);

        // ---- layer 1: read v1[p] = [x(t), h1(t-1)] ----
        if (gate) {
            float s[4][NB];
            gate_accum<14, 56>(sh + W1_OFF, sh + V1_OFF + p * V1B, j, ks, s);
            reduce4(s, mask);
            update_pair(s, ks, bz1, c1a, c1b, two, sh,
                        V1_OFF + q * V1B + ob0 * 56 + 6 + j,
                        V2_OFF + p * V2B + ob0 * 100 + j, true,
                        V1_OFF + q * V1B + ob1 * 56 + 6 + j,
                        V2_OFF + p * V2B + ob1 * 100 + j);
        } else if (pv) {
            xv = x[(size_t)(b0 + pb) * T_STEPS * IN_DIM + (t + 1) * IN_DIM + pd];
        }
        __syncthreads();

        // ---- layer 2: read v2[p] = [h1(t), h2(t-1)] ----
        if (gate) {
            float s[4][NB];
            gate_accum<25, 100>(sh + W2_OFF, sh + V2_OFF + p * V2B, j, ks, s);
            reduce4(s, mask);
            update_pair(s, ks, bz2, c2a, c2b, two, sh,
                        V2_OFF + q * V2B + ob0 * 100 + HID + j,
                        V3_OFF + p * V3B + ob0 * 100 + j, true,
                        V2_OFF + q * V2B + ob1 * 100 + HID + j,
                        V3_OFF + p * V3B + ob1 * 100 + j);
        } else if (pv) {
            sh[V1_OFF + q * V1B + pb * 56 + pd] = xv;   // commit x(t+1)
        }
        __syncthreads();

        // ---- layer 3: read v3[p] = [h2(t), h3(t-1)] ----
        if (gate) {
            float s[4][NB];
            gate_accum<25, 100>(sh + W3_OFF, sh + V3_OFF + p * V3B, j, ks, s);
            reduce4(s, mask);
            update_pair(s, ks, bz3, c3a, c3b, two, sh,
                        V3_OFF + q * V3B + ob0 * 100 + HID + j, 0, false,
                        V3_OFF + q * V3B + ob1 * 100 + HID + j, 0);
        }
        __syncthreads();
    }

    // FC: final h3 in v3 buf0 (t=511 wrote parity q=0)
    if (tid < cnt) {
        float a = fcb[0];
#pragma unroll
        for (int jj = 0; jj < HID; jj++)
            a += fcW[jj] * sh[V3_OFF + tid * 100 + HID + jj];
        out[b0 + tid] = a;
    }
}

extern "C" void kernel_launch(void* const* d_in, const int* in_sizes, int n_in,
                              void* d_out, int out_size) {
    const float* x    = (const float*)d_in[0];
    const float* Wih1 = (const float*)d_in[1];
    const float* Whh1 = (const float*)d_in[2];
    const float* bih1 = (const float*)d_in[3];
    const float* bhh1 = (const float*)d_in[4];
    const float* Wih2 = (const float*)d_in[5];
    const float* Whh2 = (const float*)d_in[6];
    const float* bih2 = (const float*)d_in[7];
    const float* bhh2 = (const float*)d_in[8];
    const float* Wih3 = (const float*)d_in[9];
    const float* Whh3 = (const float*)d_in[10];
    const float* bih3 = (const float*)d_in[11];
    const float* bhh3 = (const float*)d_in[12];
    const float* fcW  = (const float*)d_in[13];
    const float* fcb  = (const float*)d_in[14];

    size_t shbytes = (size_t)SH_FLOATS * sizeof(float);
    cudaFuncSetAttribute(lstm3_fused_kernel,
                         cudaFuncAttributeMaxDynamicSharedMemorySize,
                         (int)shbytes);
    lstm3_fused_kernel<<<GRID, NTHREADS, shbytes>>>(
        x, Wih1, Whh1, bih1, bhh1, Wih2, Whh2, bih2, bhh2,
        Wih3, Whh3, bih3, bhh3, fcW, fcb, (float*)d_out);
}